// round 2
// baseline (speedup 1.0000x reference)
#include <cuda_runtime.h>
#include <cstdint>

// GraphReversePool: out[b, v] = x[b, v2c[v]]
//   x   : [BATCH, N_CLUSTERS] fp32   (d_in[0])
//   v2c : [VERTICES] int32           (d_in[1])
//   out : [BATCH, VERTICES] fp32
//
// Strategy: each CTA owns a pair of batch rows (2 x 100 KB staged in smem),
// then streams all vertices with int4 v2c loads + float4 coalesced stores.
// Gather reads become shared-memory reads -> no gmem sector amplification.

#define BLOCK_THREADS 1024

__global__ __launch_bounds__(BLOCK_THREADS, 1)
void graph_reverse_pool_kernel(const float* __restrict__ x,
                               const int*   __restrict__ v2c,
                               float*       __restrict__ out,
                               int batch, int n_clusters, int n_vertices)
{
    extern __shared__ float srow[];   // [2][n_clusters]

    const int b0 = blockIdx.x * 2;
    const int b1 = b0 + 1;
    const bool have_b1 = (b1 < batch);

    // ---- Stage x rows into smem (float4, fully coalesced) ----
    const int nc4 = n_clusters >> 2;           // 25000/4 = 6250, exact
    {
        const float4* x0 = reinterpret_cast<const float4*>(x + (size_t)b0 * n_clusters);
        float4* s0 = reinterpret_cast<float4*>(srow);
        if (have_b1) {
            const float4* x1 = reinterpret_cast<const float4*>(x + (size_t)b1 * n_clusters);
            float4* s1 = reinterpret_cast<float4*>(srow + n_clusters);
            for (int i = threadIdx.x; i < nc4; i += BLOCK_THREADS) {
                s0[i] = x0[i];
                s1[i] = x1[i];
            }
        } else {
            for (int i = threadIdx.x; i < nc4; i += BLOCK_THREADS) {
                s0[i] = x0[i];
            }
        }
        // scalar tail (n_clusters % 4) — dead for this shape, kept for safety
        for (int i = (nc4 << 2) + threadIdx.x; i < n_clusters; i += BLOCK_THREADS) {
            srow[i] = x[(size_t)b0 * n_clusters + i];
            if (have_b1) srow[n_clusters + i] = x[(size_t)b1 * n_clusters + i];
        }
    }
    __syncthreads();

    // ---- Gather phase: int4 v2c load serves both batch rows ----
    const float* __restrict__ r0 = srow;
    const float* __restrict__ r1 = srow + n_clusters;
    const int4* __restrict__ v2c4 = reinterpret_cast<const int4*>(v2c);
    float4* __restrict__ o0 = reinterpret_cast<float4*>(out + (size_t)b0 * n_vertices);
    float4* __restrict__ o1 = reinterpret_cast<float4*>(out + (size_t)b1 * n_vertices);

    const int nv4 = n_vertices >> 2;           // 100000/4 = 25000, exact

    if (have_b1) {
        for (int v = threadIdx.x; v < nv4; v += BLOCK_THREADS) {
            const int4 c = v2c4[v];
            float4 a, b;
            a.x = r0[c.x]; a.y = r0[c.y]; a.z = r0[c.z]; a.w = r0[c.w];
            b.x = r1[c.x]; b.y = r1[c.y]; b.z = r1[c.z]; b.w = r1[c.w];
            o0[v] = a;
            o1[v] = b;
        }
        // scalar tail (n_vertices % 4) — dead for this shape
        for (int v = (nv4 << 2) + threadIdx.x; v < n_vertices; v += BLOCK_THREADS) {
            const int c = v2c[v];
            out[(size_t)b0 * n_vertices + v] = r0[c];
            out[(size_t)b1 * n_vertices + v] = r1[c];
        }
    } else {
        for (int v = threadIdx.x; v < nv4; v += BLOCK_THREADS) {
            const int4 c = v2c4[v];
            float4 a;
            a.x = r0[c.x]; a.y = r0[c.y]; a.z = r0[c.z]; a.w = r0[c.w];
            o0[v] = a;
        }
        for (int v = (nv4 << 2) + threadIdx.x; v < n_vertices; v += BLOCK_THREADS) {
            out[(size_t)b0 * n_vertices + v] = r0[v2c[v]];
        }
    }
}

extern "C" void kernel_launch(void* const* d_in, const int* in_sizes, int n_in,
                              void* d_out, int out_size)
{
    const float* x   = (const float*)d_in[0];
    const int*   v2c = (const int*)  d_in[1];
    float*       out = (float*)d_out;

    const int n_vertices = in_sizes[1];                  // 100000
    const int batch      = out_size / n_vertices;        // 1024
    const int n_clusters = in_sizes[0] / batch;          // 25000

    const int smem_bytes = 2 * n_clusters * (int)sizeof(float);  // 200000 B

    static bool attr_set = false;
    if (!attr_set) {
        cudaFuncSetAttribute(graph_reverse_pool_kernel,
                             cudaFuncAttributeMaxDynamicSharedMemorySize,
                             smem_bytes);
        attr_set = true;
    }

    const int n_pairs = (batch + 1) / 2;                 // 512 CTAs
    graph_reverse_pool_kernel<<<n_pairs, BLOCK_THREADS, smem_bytes>>>(
        x, v2c, out, batch, n_clusters, n_vertices);
}